// round 4
// baseline (speedup 1.0000x reference)
#include <cuda_runtime.h>
#include <cstdint>
#include <cstddef>

typedef unsigned long long u64;

// ---- packed f32x2 helpers (Blackwell sm_103a) ----
#define FMA2(d, a, b, c) asm("fma.rn.f32x2 %0, %1, %2, %3;" : "=l"(d) : "l"(a), "l"(b), "l"(c))
#define ADD2(d, a, b)    asm("add.rn.f32x2 %0, %1, %2;"     : "=l"(d) : "l"(a), "l"(b))

__device__ __forceinline__ u64 pack2(float lo, float hi) {
    u64 r; asm("mov.b64 %0, {%1, %2};" : "=l"(r) : "f"(lo), "f"(hi)); return r;
}
__device__ __forceinline__ float2 unpack2(u64 v) {
    float2 r; asm("mov.b64 {%0, %1}, %2;" : "=f"(r.x), "=f"(r.y) : "l"(v)); return r;
}
__device__ __forceinline__ uint32_t smem_u32(const void* p) {
    uint32_t a;
    asm("{ .reg .u64 t; cvta.to.shared.u64 t, %1; cvt.u32.u64 %0, t; }" : "=r"(a) : "l"(p));
    return a;
}
__device__ __forceinline__ void mbar_init(uint32_t mbar, uint32_t cnt) {
    asm volatile("mbarrier.init.shared.b64 [%0], %1;" :: "r"(mbar), "r"(cnt) : "memory");
}
__device__ __forceinline__ void mbar_expect_tx(uint32_t mbar, uint32_t bytes) {
    asm volatile("mbarrier.arrive.expect_tx.shared.b64 _, [%0], %1;" :: "r"(mbar), "r"(bytes) : "memory");
}
__device__ __forceinline__ void bulk_g2s(uint32_t dst, const void* src, uint32_t bytes, uint32_t mbar) {
    asm volatile("cp.async.bulk.shared::cta.global.mbarrier::complete_tx::bytes [%0], [%1], %2, [%3];"
                 :: "r"(dst), "l"(src), "r"(bytes), "r"(mbar) : "memory");
}
__device__ __forceinline__ void mbar_wait(uint32_t mbar, uint32_t parity) {
    asm volatile(
        "{\n\t"
        ".reg .pred P1;\n\t"
        "WL_%=:\n\t"
        "mbarrier.try_wait.parity.acquire.cta.shared::cta.b64 P1, [%0], %1, 0x989680;\n\t"
        "@P1 bra.uni WD_%=;\n\t"
        "bra.uni WL_%=;\n\t"
        "WD_%=:\n\t"
        "}"
        :: "r"(mbar), "r"(parity) : "memory");
}

constexpr int E_DIM    = 1024;
constexpr int MAX_ROWS = 32768;

// q scratch between kernels (1 MB)
__device__ float g_q[MAX_ROWS * 8];

// ============================================================================
// Kernel 1: h = x @ w1^T + b1 ; q = Pauli-Z cosine-string products
//   q0=c0, q1=c1, q2=c0c2, q3=c1c3, q4=c0c2c4, q5=c1c3c5, q6=c0c2c4c6,
//   q7=c0..c7  with c_i = cos(h_i)
//
// Lane layout: lane = j*8 + f (f = lane&7, j = lane>>3). Warp owns a 128-wide
// e-slice; thread (f,j) accumulates w1[f] . x over its 32-float j-sub-slice
// (x via broadcast LDS.128, chunk order rotated by (c+2j)&7 for conflict-free
// banks). Reduction over j = 2 shfl.xor (8, 16) — replaces the 9-shfl butterfly.
// x streamed HBM->SMEM via cp.async.bulk, 4-slot ring x 2 rows (8KB/stage).
// ============================================================================
constexpr int RPB1    = 64;                  // rows per block
constexpr int SROWS   = 2;                   // rows per pipeline stage
constexpr int NSLOT   = 4;                   // ring depth
constexpr int NSTAGE  = RPB1 / SROWS;        // 32
constexpr int STBYTES = SROWS * E_DIM * 4;   // 8192

__global__ void __launch_bounds__(256, 4)
ffq_phase1(const float* __restrict__ x, const float* __restrict__ w1,
           const float* __restrict__ b1, int rows)
{
    __shared__ __align__(128) float xs[NSLOT][SROWS * E_DIM];  // 32 KB ring
    __shared__ float s_part[SROWS][8][8];                      // [row][f][warp]
    __shared__ __align__(8) u64 mbar_s[NSLOT];

    const int tid  = threadIdx.x;
    const int warp = tid >> 5;
    const int lane = tid & 31;
    const int f    = lane & 7;
    const int j    = lane >> 3;

    const uint32_t mb0 = smem_u32(&mbar_s[0]);
    const uint32_t xs0 = smem_u32(&xs[0][0]);

    // rotated chunk byte-offsets within this thread's x window (computed once)
    int roff[8];
#pragma unroll
    for (int c = 0; c < 8; c++)
        roff[c] = (((c + 2 * j) & 7) << 4);      // bytes within 128B j-window

    // w1 register-resident, loaded in the same rotated order
    const int ebase = warp * 128 + j * 32;       // float index of j-window
    u64 wlo[8], whi[8];
    {
        const float* wrow = w1 + f * E_DIM + ebase;
#pragma unroll
        for (int c = 0; c < 8; c++) {
            ulonglong2 v = *reinterpret_cast<const ulonglong2*>(
                reinterpret_cast<const char*>(wrow) + roff[c]);
            wlo[c] = v.x;
            whi[c] = v.y;
        }
    }
    const float bf = b1[f];

    if (tid == 0) {
#pragma unroll
        for (int k = 0; k < NSLOT; k++) mbar_init(mb0 + k * 8, 1);
    }
    __syncthreads();

    const int    block_row0 = blockIdx.x * RPB1;
    const float* src = x + (size_t)block_row0 * E_DIM;

    // prime all ring slots
    if (tid == 0) {
#pragma unroll
        for (int k = 0; k < NSLOT; k++) {
            mbar_expect_tx(mb0 + k * 8, STBYTES);
            bulk_g2s(xs0 + k * STBYTES, src + (size_t)k * SROWS * E_DIM,
                     STBYTES, mb0 + k * 8);
        }
    }

    for (int s = 0; s < NSTAGE; s++) {
        const int slot = s & (NSLOT - 1);
        mbar_wait(mb0 + slot * 8, (s >> 2) & 1);

        const char* xbase = reinterpret_cast<const char*>(
            &xs[slot][0]) + (size_t)ebase * 4;

#pragma unroll
        for (int r = 0; r < SROWS; r++) {
            const char* xrow = xbase + r * (E_DIM * 4);
            u64 a0 = 0, a1 = 0, a2 = 0, a3 = 0;
#pragma unroll
            for (int c = 0; c < 8; c += 2) {
                ulonglong2 v0 = *reinterpret_cast<const ulonglong2*>(xrow + roff[c]);
                ulonglong2 v1 = *reinterpret_cast<const ulonglong2*>(xrow + roff[c + 1]);
                FMA2(a0, v0.x, wlo[c], a0);
                FMA2(a1, v0.y, whi[c], a1);
                FMA2(a2, v1.x, wlo[c + 1], a2);
                FMA2(a3, v1.y, whi[c + 1], a3);
            }
            ADD2(a0, a0, a1);
            ADD2(a2, a2, a3);
            ADD2(a0, a0, a2);
            float2 t = unpack2(a0);
            float p = t.x + t.y;

            // reduce over j (lanes f, f+8, f+16, f+24)
            p += __shfl_xor_sync(0xffffffffu, p, 8);
            p += __shfl_xor_sync(0xffffffffu, p, 16);

            if (lane < 8)
                s_part[r][f][warp] = p;
        }
        __syncthreads();   // stage consumed + s_part complete

        // refill this slot for stage s + NSLOT
        if (tid == 0 && s + NSLOT < NSTAGE) {
            mbar_expect_tx(mb0 + slot * 8, STBYTES);
            bulk_g2s(xs0 + slot * STBYTES,
                     src + (size_t)(s + NSLOT) * SROWS * E_DIM,
                     STBYTES, mb0 + slot * 8);
        }

        // q computation: SROWS*8 = 16 threads
        if (tid < 16) {
            const int r  = tid >> 3;
            const int ff = tid & 7;
            float h = bf;   // bf corresponds to f == tid&7 for tid<16
#pragma unroll
            for (int w = 0; w < 8; w++) h += s_part[r][ff][w];
            float c = __cosf(h);

            const int base = tid & 8;      // 8 lanes per row
            float cs[8];
#pragma unroll
            for (int jj = 0; jj < 8; jj++)
                cs[jj] = __shfl_sync(0x0000ffffu, c, base + jj);

            float q;
            if (ff == 7) {
                q = cs[0]*cs[1]*cs[2]*cs[3]*cs[4]*cs[5]*cs[6]*cs[7];
            } else {
                q = 1.0f;
#pragma unroll
                for (int jj = 0; jj < 8; jj++)
                    if (jj <= ff && ((jj ^ ff) & 1) == 0) q *= cs[jj];
            }
            g_q[(size_t)(block_row0 + s * SROWS + r) * 8 + ff] = q;
        }
        __syncthreads();   // protect s_part before next stage
    }
}

// ============================================================================
// Kernel 2: out = q @ w2^T + b2  (streaming write; w2 f-pairs in registers)
// bias folded into accumulator init: acc[i] starts as (b2[e2+i], 0).
// ============================================================================
constexpr int RPB2 = 32;

__global__ void __launch_bounds__(256, 4)
ffq_phase2(const float* __restrict__ w2, const float* __restrict__ b2,
           float* __restrict__ out, int rows)
{
    __shared__ float s_q[RPB2 * 8];    // 1 KB

    const int tid = threadIdx.x;
    const int e2  = tid * 4;

    // per-thread w2 for 4 output columns; f-pairs contiguous in w2[e][8]
    u64 wp[4][4];
#pragma unroll
    for (int i = 0; i < 4; i++) {
        ulonglong2 v0 = *reinterpret_cast<const ulonglong2*>(w2 + (e2 + i) * 8);
        ulonglong2 v1 = *reinterpret_cast<const ulonglong2*>(w2 + (e2 + i) * 8 + 4);
        wp[i][0] = v0.x; wp[i][1] = v0.y;
        wp[i][2] = v1.x; wp[i][3] = v1.y;
    }
    u64 binit[4];
    {
        float4 bv = *reinterpret_cast<const float4*>(b2 + e2);
        binit[0] = pack2(bv.x, 0.f);
        binit[1] = pack2(bv.y, 0.f);
        binit[2] = pack2(bv.z, 0.f);
        binit[3] = pack2(bv.w, 0.f);
    }

    const int row0 = blockIdx.x * RPB2;

    if (tid < 64)
        reinterpret_cast<float4*>(s_q)[tid] =
            reinterpret_cast<const float4*>(g_q + (size_t)row0 * 8)[tid];
    __syncthreads();

    float* orow = out + (size_t)row0 * E_DIM + e2;
#pragma unroll 8
    for (int r = 0; r < RPB2; r++) {
        ulonglong2 qv0 = *reinterpret_cast<const ulonglong2*>(&s_q[r * 8]);
        ulonglong2 qv1 = *reinterpret_cast<const ulonglong2*>(&s_q[r * 8 + 4]);

        float o[4];
#pragma unroll
        for (int i = 0; i < 4; i++) {
            u64 acc = binit[i];
            FMA2(acc, qv0.x, wp[i][0], acc);
            FMA2(acc, qv0.y, wp[i][1], acc);
            FMA2(acc, qv1.x, wp[i][2], acc);
            FMA2(acc, qv1.y, wp[i][3], acc);
            float2 t = unpack2(acc);
            o[i] = t.x + t.y;
        }
        *reinterpret_cast<float4*>(orow) = make_float4(o[0], o[1], o[2], o[3]);
        orow += E_DIM;
    }
}

extern "C" void kernel_launch(void* const* d_in, const int* in_sizes, int n_in,
                              void* d_out, int out_size) {
    const float* x  = (const float*)d_in[0];
    const float* w1 = (const float*)d_in[1];
    const float* b1 = (const float*)d_in[2];
    const float* w2 = (const float*)d_in[3];
    const float* b2 = (const float*)d_in[4];
    float* out = (float*)d_out;

    const int rows = in_sizes[0] / E_DIM;        // 32768

    ffq_phase1<<<rows / RPB1, 256>>>(x, w1, b1, rows);   // 512 blocks
    ffq_phase2<<<rows / RPB2, 256>>>(w2, b2, out, rows); // 1024 blocks
}

// round 5
// speedup vs baseline: 1.3895x; 1.3895x over previous
#include <cuda_runtime.h>
#include <cstdint>
#include <cstddef>

typedef unsigned long long u64;

// ---- packed f32x2 helpers (Blackwell sm_103a) ----
#define FMA2(d, a, b, c) asm("fma.rn.f32x2 %0, %1, %2, %3;" : "=l"(d) : "l"(a), "l"(b), "l"(c))
#define MUL2(d, a, b)    asm("mul.rn.f32x2 %0, %1, %2;"     : "=l"(d) : "l"(a), "l"(b))

__device__ __forceinline__ u64 pack2(float lo, float hi) {
    u64 r; asm("mov.b64 %0, {%1, %2};" : "=l"(r) : "f"(lo), "f"(hi)); return r;
}
__device__ __forceinline__ float2 unpack2(u64 v) {
    float2 r; asm("mov.b64 {%0, %1}, %2;" : "=f"(r.x), "=f"(r.y) : "l"(v)); return r;
}
__device__ __forceinline__ uint32_t smem_u32(const void* p) {
    uint32_t a;
    asm("{ .reg .u64 t; cvta.to.shared.u64 t, %1; cvt.u32.u64 %0, t; }" : "=r"(a) : "l"(p));
    return a;
}
__device__ __forceinline__ void mbar_init(uint32_t mbar, uint32_t cnt) {
    asm volatile("mbarrier.init.shared.b64 [%0], %1;" :: "r"(mbar), "r"(cnt) : "memory");
}
__device__ __forceinline__ void mbar_expect_tx(uint32_t mbar, uint32_t bytes) {
    asm volatile("mbarrier.arrive.expect_tx.shared.b64 _, [%0], %1;" :: "r"(mbar), "r"(bytes) : "memory");
}
__device__ __forceinline__ void bulk_g2s(uint32_t dst, const void* src, uint32_t bytes, uint32_t mbar) {
    asm volatile("cp.async.bulk.shared::cta.global.mbarrier::complete_tx::bytes [%0], [%1], %2, [%3];"
                 :: "r"(dst), "l"(src), "r"(bytes), "r"(mbar) : "memory");
}
__device__ __forceinline__ void mbar_wait(uint32_t mbar, uint32_t parity) {
    asm volatile(
        "{\n\t"
        ".reg .pred P1;\n\t"
        "WL_%=:\n\t"
        "mbarrier.try_wait.parity.acquire.cta.shared::cta.b64 P1, [%0], %1, 0x989680;\n\t"
        "@P1 bra.uni WD_%=;\n\t"
        "bra.uni WL_%=;\n\t"
        "WD_%=:\n\t"
        "}"
        :: "r"(mbar), "r"(parity) : "memory");
}

constexpr int E_DIM    = 1024;
constexpr int MAX_ROWS = 32768;

// q scratch between kernels (1 MB)
__device__ float g_q[MAX_ROWS * 8];

// ============================================================================
// Kernel 1: h = x @ w1^T + b1 ; q = Pauli-Z cosine-string products
//   q0=c0, q1=c1, q2=c0c2, q3=c1c3, q4=c0c2c4, q5=c1c3c5, q6=c0c2c4c6,
//   q7=c0..c7  with c_i = cos(h_i)
//
// Round-3 compute layout (thread owns 16B x-slice, 9-SHFL value-halving
// butterfly), but q computation DEFERRED to a single block epilogue:
// per-stage loop is wait -> compute -> sync -> refill (no q bubble,
// one barrier per stage instead of two).
// ============================================================================
constexpr int RPB1    = 64;                  // rows per block
constexpr int SROWS   = 2;                   // rows per pipeline stage
constexpr int NSLOT   = 4;                   // ring depth
constexpr int NSTAGE  = RPB1 / SROWS;        // 32
constexpr int STBYTES = SROWS * E_DIM * 4;   // 8192

__global__ void __launch_bounds__(256, 4)
ffq_phase1(const float* __restrict__ x, const float* __restrict__ w1,
           const float* __restrict__ b1, int rows)
{
    __shared__ __align__(128) float xs[NSLOT][SROWS * E_DIM];  // 32 KB ring
    __shared__ float s_part[RPB1][8][8];                       // [row][warp][f] 16 KB
    __shared__ __align__(8) u64 mbar_s[NSLOT];

    const int tid  = threadIdx.x;
    const int warp = tid >> 5;
    const int lane = tid & 31;

    const uint32_t mb0 = smem_u32(&mbar_s[0]);
    const uint32_t xs0 = smem_u32(&xs[0][0]);

    // w1 register-resident: warp owns e-slice [warp*128, warp*128+128)
    const int e1 = warp * 128 + lane * 4;
    u64 wa[8], wb[8];
#pragma unroll
    for (int f = 0; f < 8; f++) {
        ulonglong2 v = *reinterpret_cast<const ulonglong2*>(w1 + f * E_DIM + e1);
        wa[f] = v.x;
        wb[f] = v.y;
    }
    const float bf = b1[tid & 7];

    if (tid == 0) {
#pragma unroll
        for (int k = 0; k < NSLOT; k++) mbar_init(mb0 + k * 8, 1);
    }
    __syncthreads();

    const int    block_row0 = blockIdx.x * RPB1;
    const float* src = x + (size_t)block_row0 * E_DIM;

    // prime the ring
    if (tid == 0) {
#pragma unroll
        for (int k = 0; k < NSLOT; k++) {
            mbar_expect_tx(mb0 + k * 8, STBYTES);
            bulk_g2s(xs0 + k * STBYTES, src + (size_t)k * SROWS * E_DIM,
                     STBYTES, mb0 + k * 8);
        }
    }

    for (int s = 0; s < NSTAGE; s++) {
        const int slot = s & (NSLOT - 1);
        mbar_wait(mb0 + slot * 8, (s >> 2) & 1);

#pragma unroll
        for (int r = 0; r < SROWS; r++) {
            ulonglong2 xu = *reinterpret_cast<const ulonglong2*>(
                &xs[slot][r * E_DIM + e1]);

            float sv[8];
#pragma unroll
            for (int f = 0; f < 8; f++) {
                u64 acc;
                MUL2(acc, xu.x, wa[f]);
                FMA2(acc, xu.y, wb[f], acc);
                float2 t = unpack2(acc);
                sv[f] = t.x + t.y;
            }
            // value-halving butterfly: 8 partials -> slice-sum on lanes 4f
            {
                const bool hi = (lane & 16);
#pragma unroll
                for (int k = 0; k < 4; k++) {
                    float send = hi ? sv[k]     : sv[k + 4];
                    float keep = hi ? sv[k + 4] : sv[k];
                    sv[k] = keep + __shfl_xor_sync(0xffffffffu, send, 16);
                }
            }
            {
                const bool hi = (lane & 8);
#pragma unroll
                for (int k = 0; k < 2; k++) {
                    float send = hi ? sv[k]     : sv[k + 2];
                    float keep = hi ? sv[k + 2] : sv[k];
                    sv[k] = keep + __shfl_xor_sync(0xffffffffu, send, 8);
                }
            }
            {
                const bool hi = (lane & 4);
                float send = hi ? sv[0] : sv[1];
                float keep = hi ? sv[1] : sv[0];
                sv[0] = keep + __shfl_xor_sync(0xffffffffu, send, 4);
            }
            sv[0] += __shfl_xor_sync(0xffffffffu, sv[0], 2);
            sv[0] += __shfl_xor_sync(0xffffffffu, sv[0], 1);

            if ((lane & 3) == 0)
                s_part[s * SROWS + r][warp][lane >> 2] = sv[0];  // conflict-free STS
        }
        __syncthreads();   // slot drained + s_part rows visible later

        // refill this slot for stage s + NSLOT
        if (tid == 0 && s + NSLOT < NSTAGE) {
            mbar_expect_tx(mb0 + slot * 8, STBYTES);
            bulk_g2s(xs0 + slot * STBYTES,
                     src + (size_t)(s + NSLOT) * SROWS * E_DIM,
                     STBYTES, mb0 + slot * 8);
        }
    }

    // ---- deferred q epilogue: 64 rows x 8 f = 512 items, 2 per thread ----
#pragma unroll
    for (int it = 0; it < 2; it++) {
        const int item = it * 256 + tid;
        const int r  = item >> 3;
        const int ff = item & 7;          // == tid & 7, matches bf

        float h = bf;
#pragma unroll
        for (int w = 0; w < 8; w++) h += s_part[r][w][ff];
        float c = __cosf(h);

        const int base = lane & 24;       // 8 lanes per row within warp
        float cs[8];
#pragma unroll
        for (int jj = 0; jj < 8; jj++)
            cs[jj] = __shfl_sync(0xffffffffu, c, base + jj);

        float q;
        if (ff == 7) {
            q = cs[0]*cs[1]*cs[2]*cs[3]*cs[4]*cs[5]*cs[6]*cs[7];
        } else {
            q = 1.0f;
#pragma unroll
            for (int jj = 0; jj < 8; jj++)
                if (jj <= ff && ((jj ^ ff) & 1) == 0) q *= cs[jj];
        }
        g_q[(size_t)(block_row0 + r) * 8 + ff] = q;   // coalesced STG.32
    }
}

// ============================================================================
// Kernel 2: out = q @ w2^T + b2  (streaming write; w2 f-pairs in registers)
// RPB2=64 -> grid 512 = exactly one wave at 4 CTAs/SM (no tail).
// ============================================================================
constexpr int RPB2 = 64;

__global__ void __launch_bounds__(256, 4)
ffq_phase2(const float* __restrict__ w2, const float* __restrict__ b2,
           float* __restrict__ out, int rows)
{
    __shared__ float s_q[RPB2 * 8];    // 2 KB

    const int tid = threadIdx.x;
    const int e2  = tid * 4;

    // per-thread w2 for 4 output columns; f-pairs contiguous in w2[e][8]
    u64 wp[4][4];
#pragma unroll
    for (int i = 0; i < 4; i++) {
        ulonglong2 v0 = *reinterpret_cast<const ulonglong2*>(w2 + (e2 + i) * 8);
        ulonglong2 v1 = *reinterpret_cast<const ulonglong2*>(w2 + (e2 + i) * 8 + 4);
        wp[i][0] = v0.x; wp[i][1] = v0.y;
        wp[i][2] = v1.x; wp[i][3] = v1.y;
    }
    u64 binit[4];
    {
        float4 bv = *reinterpret_cast<const float4*>(b2 + e2);
        binit[0] = pack2(bv.x, 0.f);
        binit[1] = pack2(bv.y, 0.f);
        binit[2] = pack2(bv.z, 0.f);
        binit[3] = pack2(bv.w, 0.f);
    }

    const int row0 = blockIdx.x * RPB2;

    // stage this tile's q (RPB2*8 floats = 128 float4)
    if (tid < 128)
        reinterpret_cast<float4*>(s_q)[tid] =
            reinterpret_cast<const float4*>(g_q + (size_t)row0 * 8)[tid];
    __syncthreads();

    float* orow = out + (size_t)row0 * E_DIM + e2;
#pragma unroll 8
    for (int r = 0; r < RPB2; r++) {
        ulonglong2 qv0 = *reinterpret_cast<const ulonglong2*>(&s_q[r * 8]);
        ulonglong2 qv1 = *reinterpret_cast<const ulonglong2*>(&s_q[r * 8 + 4]);

        float o[4];
#pragma unroll
        for (int i = 0; i < 4; i++) {
            u64 acc = binit[i];
            FMA2(acc, qv0.x, wp[i][0], acc);
            FMA2(acc, qv0.y, wp[i][1], acc);
            FMA2(acc, qv1.x, wp[i][2], acc);
            FMA2(acc, qv1.y, wp[i][3], acc);
            float2 t = unpack2(acc);
            o[i] = t.x + t.y;
        }
        *reinterpret_cast<float4*>(orow) = make_float4(o[0], o[1], o[2], o[3]);
        orow += E_DIM;
    }
}

extern "C" void kernel_launch(void* const* d_in, const int* in_sizes, int n_in,
                              void* d_out, int out_size) {
    const float* x  = (const float*)d_in[0];
    const float* w1 = (const float*)d_in[1];
    const float* b1 = (const float*)d_in[2];
    const float* w2 = (const float*)d_in[3];
    const float* b2 = (const float*)d_in[4];
    float* out = (float*)d_out;

    const int rows = in_sizes[0] / E_DIM;        // 32768

    ffq_phase1<<<rows / RPB1, 256>>>(x, w1, b1, rows);   // 512 blocks
    ffq_phase2<<<rows / RPB2, 256>>>(w2, b2, out, rows); // 512 blocks
}

// round 7
// speedup vs baseline: 1.4365x; 1.0338x over previous
#include <cuda_runtime.h>
#include <cstdint>
#include <cstddef>

typedef unsigned long long u64;

// ---- packed f32x2 helpers (Blackwell sm_103a) ----
#define FMA2(d, a, b, c) asm("fma.rn.f32x2 %0, %1, %2, %3;" : "=l"(d) : "l"(a), "l"(b), "l"(c))
#define MUL2(d, a, b)    asm("mul.rn.f32x2 %0, %1, %2;"     : "=l"(d) : "l"(a), "l"(b))
#define ADD2(d, a, b)    asm("add.rn.f32x2 %0, %1, %2;"     : "=l"(d) : "l"(a), "l"(b))

__device__ __forceinline__ u64 pack2(float lo, float hi) {
    u64 r; asm("mov.b64 %0, {%1, %2};" : "=l"(r) : "f"(lo), "f"(hi)); return r;
}
__device__ __forceinline__ float2 unpack2(u64 v) {
    float2 r; asm("mov.b64 {%0, %1}, %2;" : "=f"(r.x), "=f"(r.y) : "l"(v)); return r;
}
__device__ __forceinline__ void stg_cs_v4(float* p, float4 v) {
    asm volatile("st.global.cs.v4.f32 [%0], {%1, %2, %3, %4};"
                 :: "l"(p), "f"(v.x), "f"(v.y), "f"(v.z), "f"(v.w) : "memory");
}
__device__ __forceinline__ uint32_t smem_u32(const void* p) {
    uint32_t a;
    asm("{ .reg .u64 t; cvta.to.shared.u64 t, %1; cvt.u32.u64 %0, t; }" : "=r"(a) : "l"(p));
    return a;
}
__device__ __forceinline__ void mbar_init(uint32_t mbar, uint32_t cnt) {
    asm volatile("mbarrier.init.shared.b64 [%0], %1;" :: "r"(mbar), "r"(cnt) : "memory");
}
__device__ __forceinline__ void mbar_expect_tx(uint32_t mbar, uint32_t bytes) {
    asm volatile("mbarrier.arrive.expect_tx.shared.b64 _, [%0], %1;" :: "r"(mbar), "r"(bytes) : "memory");
}
__device__ __forceinline__ void bulk_g2s(uint32_t dst, const void* src, uint32_t bytes, uint32_t mbar) {
    asm volatile("cp.async.bulk.shared::cta.global.mbarrier::complete_tx::bytes [%0], [%1], %2, [%3];"
                 :: "r"(dst), "l"(src), "r"(bytes), "r"(mbar) : "memory");
}
__device__ __forceinline__ void mbar_wait(uint32_t mbar, uint32_t parity) {
    asm volatile(
        "{\n\t"
        ".reg .pred P1;\n\t"
        "WL_%=:\n\t"
        "mbarrier.try_wait.parity.acquire.cta.shared::cta.b64 P1, [%0], %1, 0x989680;\n\t"
        "@P1 bra.uni WD_%=;\n\t"
        "bra.uni WL_%=;\n\t"
        "WD_%=:\n\t"
        "}"
        :: "r"(mbar), "r"(parity) : "memory");
}

constexpr int E_DIM    = 1024;
constexpr int MAX_ROWS = 32768;

// q scratch between kernels (1 MB)
__device__ float g_q[MAX_ROWS * 8];

// ============================================================================
// Kernel 1: h = x @ w1^T + b1 ; q = Pauli-Z cosine-string products
//   q0=c0, q1=c1, q2=c0c2, q3=c1c3, q4=c0c2c4, q5=c1c3c5, q6=c0c2c4c6,
//   q7=c0..c7  with c_i = cos(h_i)
//
// Accumulators hold (f_even, f_odd) pairs: acc[p] = (dot_f{2p}, dot_f{2p+1}).
// Warp reduction = packed value-halving on 4 u64:
//   xor16 (halve 4->2), xor8 (2->1), then xor4/2/1 plain u64 adds.
// Lane (lane&7)==0 stores its finished pair (p = lane>>3) with one STS.64.
// SROWS=4 rows in flight per warp for SHFL-chain ILP; 2-slot TMA ring.
// ============================================================================
constexpr int RPB1    = 64;                  // rows per block
constexpr int SROWS   = 4;                   // rows per pipeline stage
constexpr int NSLOT   = 2;                   // ring depth
constexpr int NSTAGE  = RPB1 / SROWS;        // 16
constexpr int STBYTES = SROWS * E_DIM * 4;   // 16384

__global__ void __launch_bounds__(256, 4)
ffq_phase1(const float* __restrict__ x, const float* __restrict__ w1,
           const float* __restrict__ b1, int rows)
{
    __shared__ __align__(128) float xs[NSLOT][SROWS * E_DIM];  // 32 KB ring
    __shared__ __align__(16) float s_part[RPB1][8][8];         // [row][warp][f] 16 KB
    __shared__ __align__(8) u64 mbar_s[NSLOT];

    const int tid  = threadIdx.x;
    const int warp = tid >> 5;
    const int lane = tid & 31;

    const uint32_t mb0 = smem_u32(&mbar_s[0]);
    const uint32_t xs0 = smem_u32(&xs[0][0]);

    // w1 packed by f-pair: wpk[p][e] = (w1[2p][e1+e], w1[2p+1][e1+e])
    const int e1 = warp * 128 + lane * 4;
    u64 wpk[4][4];
#pragma unroll
    for (int p = 0; p < 4; p++) {
        const float* w0 = w1 + (2 * p)     * E_DIM + e1;
        const float* w1r= w1 + (2 * p + 1) * E_DIM + e1;
#pragma unroll
        for (int e = 0; e < 4; e++)
            wpk[p][e] = pack2(w0[e], w1r[e]);
    }
    const float bf = b1[tid & 7];

    if (tid == 0) {
#pragma unroll
        for (int k = 0; k < NSLOT; k++) mbar_init(mb0 + k * 8, 1);
    }
    __syncthreads();

    const int    block_row0 = blockIdx.x * RPB1;
    const float* src = x + (size_t)block_row0 * E_DIM;

    // prime the ring
    if (tid == 0) {
#pragma unroll
        for (int k = 0; k < NSLOT; k++) {
            mbar_expect_tx(mb0 + k * 8, STBYTES);
            bulk_g2s(xs0 + k * STBYTES, src + (size_t)k * SROWS * E_DIM,
                     STBYTES, mb0 + k * 8);
        }
    }

    const bool hi16 = (lane & 16);
    const bool hi8  = (lane & 8);

    for (int s = 0; s < NSTAGE; s++) {
        const int slot = s & (NSLOT - 1);
        mbar_wait(mb0 + slot * 8, (s >> 1) & 1);

#pragma unroll
        for (int r = 0; r < SROWS; r++) {
            float4 xv = *reinterpret_cast<const float4*>(
                &xs[slot][r * E_DIM + e1]);
            u64 xd[4];
            xd[0] = pack2(xv.x, xv.x);
            xd[1] = pack2(xv.y, xv.y);
            xd[2] = pack2(xv.z, xv.z);
            xd[3] = pack2(xv.w, xv.w);

            u64 v0, v1, v2, v3;
            MUL2(v0, xd[0], wpk[0][0]);
            MUL2(v1, xd[0], wpk[1][0]);
            MUL2(v2, xd[0], wpk[2][0]);
            MUL2(v3, xd[0], wpk[3][0]);
#pragma unroll
            for (int e = 1; e < 4; e++) {
                FMA2(v0, xd[e], wpk[0][e], v0);
                FMA2(v1, xd[e], wpk[1][e], v1);
                FMA2(v2, xd[e], wpk[2][e], v2);
                FMA2(v3, xd[e], wpk[3][e], v3);
            }

            // packed value-halving butterfly on 4 u64 pair-accumulators
            // xor16: lo lanes keep pairs {0,1}, hi lanes keep {2,3}
            {
                u64 s0 = hi16 ? v0 : v2;
                u64 s1 = hi16 ? v1 : v3;
                u64 k0 = hi16 ? v2 : v0;
                u64 k1 = hi16 ? v3 : v1;
                u64 r0 = __shfl_xor_sync(0xffffffffu, s0, 16);
                u64 r1 = __shfl_xor_sync(0xffffffffu, s1, 16);
                ADD2(v0, k0, r0);
                ADD2(v1, k1, r1);
            }
            // xor8: bit3=0 keeps first pair of the surviving two
            u64 w;
            {
                u64 sv = hi8 ? v0 : v1;
                u64 kv = hi8 ? v1 : v0;
                u64 rv = __shfl_xor_sync(0xffffffffu, sv, 8);
                ADD2(w, kv, rv);
            }
            // xor4 / xor2 / xor1: plain u64 reductions
            {
                u64 rv = __shfl_xor_sync(0xffffffffu, w, 4);
                ADD2(w, w, rv);
                rv = __shfl_xor_sync(0xffffffffu, w, 2);
                ADD2(w, w, rv);
                rv = __shfl_xor_sync(0xffffffffu, w, 1);
                ADD2(w, w, rv);
            }
            // lane 0/8/16/24 holds pair p = lane>>3 fully summed
            if ((lane & 7) == 0) {
                const int p = lane >> 3;
                *reinterpret_cast<u64*>(&s_part[s * SROWS + r][warp][2 * p]) = w;
            }
        }
        __syncthreads();   // slot drained; s_part visible at epilogue

        // refill this slot for stage s + NSLOT
        if (tid == 0 && s + NSLOT < NSTAGE) {
            mbar_expect_tx(mb0 + slot * 8, STBYTES);
            bulk_g2s(xs0 + slot * STBYTES,
                     src + (size_t)(s + NSLOT) * SROWS * E_DIM,
                     STBYTES, mb0 + slot * 8);
        }
    }

    // ---- deferred q epilogue: 64 rows x 8 f = 512 items, 2 per thread ----
#pragma unroll
    for (int it = 0; it < 2; it++) {
        const int item = it * 256 + tid;
        const int r  = item >> 3;
        const int ff = item & 7;          // == tid & 7, matches bf

        float h = bf;
#pragma unroll
        for (int w = 0; w < 8; w++) h += s_part[r][w][ff];
        float c = __cosf(h);

        const int base = lane & 24;       // 8 lanes per row within warp
        float cs[8];
#pragma unroll
        for (int jj = 0; jj < 8; jj++)
            cs[jj] = __shfl_sync(0xffffffffu, c, base + jj);

        float q;
        if (ff == 7) {
            q = cs[0]*cs[1]*cs[2]*cs[3]*cs[4]*cs[5]*cs[6]*cs[7];
        } else {
            q = 1.0f;
#pragma unroll
            for (int jj = 0; jj < 8; jj++)
                if (jj <= ff && ((jj ^ ff) & 1) == 0) q *= cs[jj];
        }
        g_q[(size_t)(block_row0 + r) * 8 + ff] = q;   // coalesced STG.32
    }
}

// ============================================================================
// Kernel 2: out = q @ w2^T + b2  (streaming write; w2 f-pairs in registers)
// Stores via st.global.cs (evict-first) so the 134MB out stream doesn't
// thrash L2 against next-replay x reads.
// ============================================================================
constexpr int RPB2 = 64;

__global__ void __launch_bounds__(256, 4)
ffq_phase2(const float* __restrict__ w2, const float* __restrict__ b2,
           float* __restrict__ out, int rows)
{
    __shared__ float s_q[RPB2 * 8];    // 2 KB

    const int tid = threadIdx.x;
    const int e2  = tid * 4;

    // per-thread w2 for 4 output columns; f-pairs contiguous in w2[e][8]
    u64 wp[4][4];
#pragma unroll
    for (int i = 0; i < 4; i++) {
        ulonglong2 v0 = *reinterpret_cast<const ulonglong2*>(w2 + (e2 + i) * 8);
        ulonglong2 v1 = *reinterpret_cast<const ulonglong2*>(w2 + (e2 + i) * 8 + 4);
        wp[i][0] = v0.x; wp[i][1] = v0.y;
        wp[i][2] = v1.x; wp[i][3] = v1.y;
    }
    u64 binit[4];
    {
        float4 bv = *reinterpret_cast<const float4*>(b2 + e2);
        binit[0] = pack2(bv.x, 0.f);
        binit[1] = pack2(bv.y, 0.f);
        binit[2] = pack2(bv.z, 0.f);
        binit[3] = pack2(bv.w, 0.f);
    }

    const int row0 = blockIdx.x * RPB2;

    // stage this tile's q (RPB2*8 floats = 128 float4)
    if (tid < 128)
        reinterpret_cast<float4*>(s_q)[tid] =
            reinterpret_cast<const float4*>(g_q + (size_t)row0 * 8)[tid];
    __syncthreads();

    float* orow = out + (size_t)row0 * E_DIM + e2;
#pragma unroll 8
    for (int r = 0; r < RPB2; r++) {
        ulonglong2 qv0 = *reinterpret_cast<const ulonglong2*>(&s_q[r * 8]);
        ulonglong2 qv1 = *reinterpret_cast<const ulonglong2*>(&s_q[r * 8 + 4]);

        float o[4];
#pragma unroll
        for (int i = 0; i < 4; i++) {
            u64 acc = binit[i];
            FMA2(acc, qv0.x, wp[i][0], acc);
            FMA2(acc, qv0.y, wp[i][1], acc);
            FMA2(acc, qv1.x, wp[i][2], acc);
            FMA2(acc, qv1.y, wp[i][3], acc);
            float2 t = unpack2(acc);
            o[i] = t.x + t.y;
        }
        stg_cs_v4(orow, make_float4(o[0], o[1], o[2], o[3]));
        orow += E_DIM;
    }
}

extern "C" void kernel_launch(void* const* d_in, const int* in_sizes, int n_in,
                              void* d_out, int out_size) {
    const float* x  = (const float*)d_in[0];
    const float* w1 = (const float*)d_in[1];
    const float* b1 = (const float*)d_in[2];
    const float* w2 = (const float*)d_in[3];
    const float* b2 = (const float*)d_in[4];
    float* out = (float*)d_out;

    const int rows = in_sizes[0] / E_DIM;        // 32768

    ffq_phase1<<<rows / RPB1, 256>>>(x, w1, b1, rows);   // 512 blocks
    ffq_phase2<<<rows / RPB2, 256>>>(w2, b2, out, rows); // 512 blocks
}

// round 8
// speedup vs baseline: 1.5850x; 1.1033x over previous
#include <cuda_runtime.h>
#include <cstdint>
#include <cstddef>

typedef unsigned long long u64;

// ---- packed f32x2 helpers (Blackwell sm_103a) ----
#define FMA2(d, a, b, c) asm("fma.rn.f32x2 %0, %1, %2, %3;" : "=l"(d) : "l"(a), "l"(b), "l"(c))
#define MUL2(d, a, b)    asm("mul.rn.f32x2 %0, %1, %2;"     : "=l"(d) : "l"(a), "l"(b))
#define ADD2(d, a, b)    asm("add.rn.f32x2 %0, %1, %2;"     : "=l"(d) : "l"(a), "l"(b))

__device__ __forceinline__ u64 pack2(float lo, float hi) {
    u64 r; asm("mov.b64 %0, {%1, %2};" : "=l"(r) : "f"(lo), "f"(hi)); return r;
}
__device__ __forceinline__ float2 unpack2(u64 v) {
    float2 r; asm("mov.b64 {%0, %1}, %2;" : "=f"(r.x), "=f"(r.y) : "l"(v)); return r;
}
__device__ __forceinline__ void stg_cs_v4(float* p, float4 v) {
    asm volatile("st.global.cs.v4.f32 [%0], {%1, %2, %3, %4};"
                 :: "l"(p), "f"(v.x), "f"(v.y), "f"(v.z), "f"(v.w) : "memory");
}
__device__ __forceinline__ uint32_t smem_u32(const void* p) {
    uint32_t a;
    asm("{ .reg .u64 t; cvta.to.shared.u64 t, %1; cvt.u32.u64 %0, t; }" : "=r"(a) : "l"(p));
    return a;
}
__device__ __forceinline__ void mbar_init(uint32_t mbar, uint32_t cnt) {
    asm volatile("mbarrier.init.shared.b64 [%0], %1;" :: "r"(mbar), "r"(cnt) : "memory");
}
__device__ __forceinline__ void mbar_expect_tx(uint32_t mbar, uint32_t bytes) {
    asm volatile("mbarrier.arrive.expect_tx.shared.b64 _, [%0], %1;" :: "r"(mbar), "r"(bytes) : "memory");
}
__device__ __forceinline__ void bulk_g2s(uint32_t dst, const void* src, uint32_t bytes, uint32_t mbar) {
    asm volatile("cp.async.bulk.shared::cta.global.mbarrier::complete_tx::bytes [%0], [%1], %2, [%3];"
                 :: "r"(dst), "l"(src), "r"(bytes), "r"(mbar) : "memory");
}
__device__ __forceinline__ void mbar_wait(uint32_t mbar, uint32_t parity) {
    asm volatile(
        "{\n\t"
        ".reg .pred P1;\n\t"
        "WL_%=:\n\t"
        "mbarrier.try_wait.parity.acquire.cta.shared::cta.b64 P1, [%0], %1, 0x989680;\n\t"
        "@P1 bra.uni WD_%=;\n\t"
        "bra.uni WL_%=;\n\t"
        "WD_%=:\n\t"
        "}"
        :: "r"(mbar), "r"(parity) : "memory");
}

constexpr int E_DIM = 1024;

// ============================================================================
// Fused: h = x@w1^T + b1 ; q = Pauli-Z cosine strings ; out = q@w2^T + b2
//   q0=c0, q1=c1, q2=c0c2, q3=c1c3, q4=c0c2c4, q5=c1c3c5, q6=c0c2c4c6,
//   q7=c0..c7  with c_i = cos(h_i)
//
// Per 64-row block:
//   [A] x streamed HBM->SMEM (cp.async.bulk 2-slot ring, 4 rows/stage);
//       packed f-pair dot products + packed value-halving butterfly ->
//       per-warp partials persisted in s_part (deferred-q scheme).
//   [B] q epilogue: 512 items over 256 threads -> s_q (smem, no gmem trip).
//   [C] out tail: w2 f-pairs in regs (lifetime starts after [A] so w1 regs
//       are dead), 64 rows x 4 cols/thread, st.global.cs.
// Fusing interleaves the read-stream [A] and write-stream [C] across the
// chip's CTA waves -> mixed HBM traffic instead of bursty phases.
// ============================================================================
constexpr int RPB     = 64;                  // rows per block
constexpr int SROWS   = 4;                   // rows per pipeline stage
constexpr int NSLOT   = 2;                   // ring depth
constexpr int NSTAGE  = RPB / SROWS;         // 16
constexpr int STBYTES = SROWS * E_DIM * 4;   // 16384

__global__ void __launch_bounds__(256, 4)
ffq_fused(const float* __restrict__ x,  const float* __restrict__ w1,
          const float* __restrict__ b1, const float* __restrict__ w2,
          const float* __restrict__ b2, float* __restrict__ out, int rows)
{
    __shared__ __align__(128) float xs[NSLOT][SROWS * E_DIM];  // 32 KB ring
    __shared__ __align__(16) float s_part[RPB][8][8];          // 16 KB
    __shared__ __align__(16) float s_q[RPB][8];                // 2 KB
    __shared__ __align__(8) u64 mbar_s[NSLOT];

    const int tid  = threadIdx.x;
    const int warp = tid >> 5;
    const int lane = tid & 31;

    const uint32_t mb0 = smem_u32(&mbar_s[0]);
    const uint32_t xs0 = smem_u32(&xs[0][0]);

    // ---- [A] phase-1 weights: f-pair packed, warp owns 128-wide e-slice ----
    const int e1 = warp * 128 + lane * 4;
    u64 wpk[4][4];
#pragma unroll
    for (int p = 0; p < 4; p++) {
        const float* w0 = w1 + (2 * p)     * E_DIM + e1;
        const float* w1r= w1 + (2 * p + 1) * E_DIM + e1;
#pragma unroll
        for (int e = 0; e < 4; e++)
            wpk[p][e] = pack2(w0[e], w1r[e]);
    }
    const float bf = b1[tid & 7];

    if (tid == 0) {
#pragma unroll
        for (int k = 0; k < NSLOT; k++) mbar_init(mb0 + k * 8, 1);
    }
    __syncthreads();

    const int    block_row0 = blockIdx.x * RPB;
    const float* src = x + (size_t)block_row0 * E_DIM;

    if (tid == 0) {
#pragma unroll
        for (int k = 0; k < NSLOT; k++) {
            mbar_expect_tx(mb0 + k * 8, STBYTES);
            bulk_g2s(xs0 + k * STBYTES, src + (size_t)k * SROWS * E_DIM,
                     STBYTES, mb0 + k * 8);
        }
    }

    const bool hi16 = (lane & 16);
    const bool hi8  = (lane & 8);

    for (int s = 0; s < NSTAGE; s++) {
        const int slot = s & (NSLOT - 1);
        mbar_wait(mb0 + slot * 8, (s >> 1) & 1);

#pragma unroll
        for (int r = 0; r < SROWS; r++) {
            float4 xv = *reinterpret_cast<const float4*>(
                &xs[slot][r * E_DIM + e1]);
            u64 xd[4];
            xd[0] = pack2(xv.x, xv.x);
            xd[1] = pack2(xv.y, xv.y);
            xd[2] = pack2(xv.z, xv.z);
            xd[3] = pack2(xv.w, xv.w);

            u64 v0, v1, v2, v3;
            MUL2(v0, xd[0], wpk[0][0]);
            MUL2(v1, xd[0], wpk[1][0]);
            MUL2(v2, xd[0], wpk[2][0]);
            MUL2(v3, xd[0], wpk[3][0]);
#pragma unroll
            for (int e = 1; e < 4; e++) {
                FMA2(v0, xd[e], wpk[0][e], v0);
                FMA2(v1, xd[e], wpk[1][e], v1);
                FMA2(v2, xd[e], wpk[2][e], v2);
                FMA2(v3, xd[e], wpk[3][e], v3);
            }

            // packed value-halving butterfly on 4 u64 pair-accumulators
            {
                u64 s0 = hi16 ? v0 : v2;
                u64 s1 = hi16 ? v1 : v3;
                u64 k0 = hi16 ? v2 : v0;
                u64 k1 = hi16 ? v3 : v1;
                u64 r0 = __shfl_xor_sync(0xffffffffu, s0, 16);
                u64 r1 = __shfl_xor_sync(0xffffffffu, s1, 16);
                ADD2(v0, k0, r0);
                ADD2(v1, k1, r1);
            }
            u64 w;
            {
                u64 sv = hi8 ? v0 : v1;
                u64 kv = hi8 ? v1 : v0;
                u64 rv = __shfl_xor_sync(0xffffffffu, sv, 8);
                ADD2(w, kv, rv);
            }
            {
                u64 rv = __shfl_xor_sync(0xffffffffu, w, 4);
                ADD2(w, w, rv);
                rv = __shfl_xor_sync(0xffffffffu, w, 2);
                ADD2(w, w, rv);
                rv = __shfl_xor_sync(0xffffffffu, w, 1);
                ADD2(w, w, rv);
            }
            if ((lane & 7) == 0) {
                const int p = lane >> 3;
                *reinterpret_cast<u64*>(&s_part[s * SROWS + r][warp][2 * p]) = w;
            }
        }
        __syncthreads();   // slot drained; s_part row-group committed

        if (tid == 0 && s + NSLOT < NSTAGE) {
            mbar_expect_tx(mb0 + slot * 8, STBYTES);
            bulk_g2s(xs0 + slot * STBYTES,
                     src + (size_t)(s + NSLOT) * SROWS * E_DIM,
                     STBYTES, mb0 + slot * 8);
        }
    }

    // ---- [B] q epilogue: 64 rows x 8 f = 512 items, 2 per thread ----
#pragma unroll
    for (int it = 0; it < 2; it++) {
        const int item = it * 256 + tid;
        const int r  = item >> 3;
        const int ff = item & 7;          // == tid & 7, matches bf

        float h = bf;
#pragma unroll
        for (int w = 0; w < 8; w++) h += s_part[r][w][ff];
        float c = __cosf(h);

        const int base = lane & 24;
        float cs[8];
#pragma unroll
        for (int jj = 0; jj < 8; jj++)
            cs[jj] = __shfl_sync(0xffffffffu, c, base + jj);

        float q;
        if (ff == 7) {
            q = cs[0]*cs[1]*cs[2]*cs[3]*cs[4]*cs[5]*cs[6]*cs[7];
        } else {
            q = 1.0f;
#pragma unroll
            for (int jj = 0; jj < 8; jj++)
                if (jj <= ff && ((jj ^ ff) & 1) == 0) q *= cs[jj];
        }
        s_q[r][ff] = q;
    }
    __syncthreads();

    // ---- [C] out tail: w2 f-pairs in regs (loaded after w1 regs die) ----
    const int e2 = tid * 4;
    u64 wp[4][4];
#pragma unroll
    for (int i = 0; i < 4; i++) {
        ulonglong2 v0 = *reinterpret_cast<const ulonglong2*>(w2 + (e2 + i) * 8);
        ulonglong2 v1 = *reinterpret_cast<const ulonglong2*>(w2 + (e2 + i) * 8 + 4);
        wp[i][0] = v0.x; wp[i][1] = v0.y;
        wp[i][2] = v1.x; wp[i][3] = v1.y;
    }
    u64 binit[4];
    {
        float4 bv = *reinterpret_cast<const float4*>(b2 + e2);
        binit[0] = pack2(bv.x, 0.f);
        binit[1] = pack2(bv.y, 0.f);
        binit[2] = pack2(bv.z, 0.f);
        binit[3] = pack2(bv.w, 0.f);
    }

    float* orow = out + (size_t)block_row0 * E_DIM + e2;
#pragma unroll 8
    for (int r = 0; r < RPB; r++) {
        ulonglong2 qv0 = *reinterpret_cast<const ulonglong2*>(&s_q[r][0]);
        ulonglong2 qv1 = *reinterpret_cast<const ulonglong2*>(&s_q[r][4]);

        float o[4];
#pragma unroll
        for (int i = 0; i < 4; i++) {
            u64 acc = binit[i];
            FMA2(acc, qv0.x, wp[i][0], acc);
            FMA2(acc, qv0.y, wp[i][1], acc);
            FMA2(acc, qv1.x, wp[i][2], acc);
            FMA2(acc, qv1.y, wp[i][3], acc);
            float2 t = unpack2(acc);
            o[i] = t.x + t.y;
        }
        stg_cs_v4(orow, make_float4(o[0], o[1], o[2], o[3]));
        orow += E_DIM;
    }
}

extern "C" void kernel_launch(void* const* d_in, const int* in_sizes, int n_in,
                              void* d_out, int out_size) {
    const float* x  = (const float*)d_in[0];
    const float* w1 = (const float*)d_in[1];
    const float* b1 = (const float*)d_in[2];
    const float* w2 = (const float*)d_in[3];
    const float* b2 = (const float*)d_in[4];
    float* out = (float*)d_out;

    const int rows = in_sizes[0] / E_DIM;        // 32768
    ffq_fused<<<rows / RPB, 256>>>(x, w1, b1, w2, b2, out, rows);  // 512 blocks
}